// round 1
// baseline (speedup 1.0000x reference)
#include <cuda_runtime.h>
#include <math.h>

#define PI 3.141592653589793238462643383279502884

// problem sizes
#define NB    128     // 2*B_IN (beta and alpha samples of input sphere)
#define NSPEC 400     // B_OUT^2
#define LMAX  20      // B_OUT
#define NGRID 24
#define FI    16
#define FO    32
#define NBATCH 16
#define TB    40      // 2*B_INV
#define NFREQ 39      // frequencies -19..19
#define NS2   10660   // sum_{l<20} (2l+1)^2
#define NDINV 426400  // 40 * NS2

// cumulative (2l+1)^2 offsets
__constant__ int c_base[21] = {0,1,10,35,84,165,286,455,680,969,1330,1771,
                               2300,2925,3654,4495,5456,6545,7770,9139,10660};

// ---- device scratch (static, allocation-free) ----
__device__ double g_lg[64];                 // lgamma(k+1)
__device__ double g_w[NB];                  // quadrature weights
__device__ float  g_ws2T[NSPEC*NB];         // [lm][b]
__device__ float2 g_Fk[NSPEC*NGRID];        // [lm][p]
__device__ float  g_dinv[NDINV];            // per-l blocks: [beta][mi][ni]
__device__ float2 g_CY[NSPEC*FI*FO];        // conj(y): [lm][i][o]
__device__ float2 g_XF[NFREQ*NBATCH*FI*NB]; // [mf][zi][b]
__device__ float2 g_XL[NSPEC*NBATCH*FI];    // [lm][zi]
__device__ float2 g_ZL[NBATCH*NS2*FO];      // [z][s][o]

// Wigner-d via term-ratio recurrence (double; 1 exp per element)
__device__ __forceinline__ double wigner_d_fn(int l, int m, int n, double beta,
                                              const double* lg) {
    double cb = cos(0.5*beta), sb = sin(0.5*beta);
    double lcb = log(cb), lsb = log(sb);
    int s0 = max(0, n - m), s1 = min(l + n, l - m);
    double pref = 0.5*(lg[l+m] + lg[l-m] + lg[l+n] + lg[l-n]);
    double c0 = pref - (lg[l+n-s0] + lg[s0] + lg[m-n+s0] + lg[l-m-s0]);
    double t = exp(c0 + (double)(2*l + n - m - 2*s0)*lcb
                      + (double)(m - n + 2*s0)*lsb);
    if ((m - n + s0) & 1) t = -t;
    double r = (sb*sb)/(cb*cb);
    double val = 0.0;
    for (int s = s0;; ++s) {
        val += t;
        if (s >= s1) break;
        t *= -((double)((l+n-s)*(l-m-s)) * r) / (double)((s+1)*(m-n+s+1));
    }
    return val;
}

__device__ __forceinline__ int l_from_lm(int lm) {
    int l = 0;
    while ((l+1)*(l+1) <= lm) l++;
    return l;
}

// ---- constants kernels ----
__global__ void k_tables() {
    int t = threadIdx.x;
    if (t < 64) g_lg[t] = lgamma((double)t + 1.0);
    // quadrature weights for 2*B_IN beta samples
    double theta = PI * (2.0*t + 1.0) / 256.0;
    double ssum = 0.0;
    for (int k = 0; k < 64; k++)
        ssum += sin((2.0*k + 1.0)*theta) / (2.0*k + 1.0);
    g_w[t] = (2.0/64.0) * sin(theta) * ssum;
}

__global__ void k_ws2() {
    __shared__ double lg[64];
    if (threadIdx.x < 64) lg[threadIdx.x] = g_lg[threadIdx.x];
    __syncthreads();
    int idx = blockIdx.x*blockDim.x + threadIdx.x;
    if (idx >= NSPEC*NB) return;
    int lm = idx >> 7, b = idx & 127;
    int l = l_from_lm(lm);
    int m = lm - l*l - l;
    double beta = PI * (2.0*b + 1.0) / 256.0;
    double d = wigner_d_fn(l, m, 0, beta, lg);
    g_ws2T[lm*NB + b] = (float)(d * g_w[b]);
}

__global__ void k_fk() {
    __shared__ double lg[64];
    if (threadIdx.x < 64) lg[threadIdx.x] = g_lg[threadIdx.x];
    __syncthreads();
    int idx = blockIdx.x*blockDim.x + threadIdx.x;
    if (idx >= NSPEC*NGRID) return;
    int lm = idx / NGRID, p = idx % NGRID;
    int l = l_from_lm(lm);
    int m = lm - l*l - l;
    int bi = p >> 3, ai = p & 7;
    double beta = (bi + 1) * PI / 24.0;
    double alpha = ai * (PI / 4.0);
    double d = wigner_d_fn(l, m, 0, beta, lg);
    double sa, ca;
    sincos((double)m * alpha, &sa, &ca);
    g_Fk[lm*NGRID + p] = make_float2((float)(d*ca), (float)(-d*sa));
}

__global__ void k_dinv() {
    __shared__ double lg[64];
    if (threadIdx.x < 64) lg[threadIdx.x] = g_lg[threadIdx.x];
    __syncthreads();
    int idx = blockIdx.x*blockDim.x + threadIdx.x;
    if (idx >= NDINV) return;
    int l = 0;
    while (idx >= 40*c_base[l+1]) l++;
    int rem = idx - 40*c_base[l];
    int w = 2*l + 1, w2 = w*w;
    int bidx = rem / w2;
    int r2 = rem - bidx*w2;
    int mi = r2 / w, ni = r2 - mi*w;
    double beta = PI * (2.0*bidx + 1.0) / 80.0;
    double d = (double)(2*l + 1) * wigner_d_fn(l, mi - l, ni - l, beta, lg);
    g_dinv[idx] = (float)d;
}

// CY[lm][i][o] = SCALING * sum_p kernel[i][o][p] * conj(Fk[lm][p])
__global__ void k_y(const float* __restrict__ kern) {
    int idx = blockIdx.x*blockDim.x + threadIdx.x;
    if (idx >= NSPEC*FI*FO) return;
    int lm = idx >> 9, io = idx & 511;
    const float SC = (float)(1.0/sqrt(15000.0)); // 1/sqrt(24*16*20^4/64^2)
    float re = 0.f, im = 0.f;
    #pragma unroll
    for (int p = 0; p < NGRID; p++) {
        float kv = kern[io*NGRID + p];
        float2 fk = g_Fk[lm*NGRID + p];
        re += kv * fk.x;
        im -= kv * fk.y;  // conj
    }
    g_CY[idx] = make_float2(SC*re, SC*im);
}

// XF[mf][zi][b] = sum_a x[zi][b][a] * e^{-2pi i (mf-19) a / 128}
__global__ void k_xf(const float* __restrict__ x) {
    extern __shared__ float sm[];
    float* sx   = sm;              // 128 * 129 (padded)
    float* c128 = sm + NB*129;     // 128
    float* s128 = c128 + NB;       // 128
    int zi = blockIdx.x;
    const float* xr = x + (size_t)zi * NB * NB;
    for (int t = threadIdx.x; t < NB*NB; t += blockDim.x) {
        int b = t >> 7, a = t & 127;
        sx[b*129 + a] = xr[t];
    }
    if (threadIdx.x < NB) {
        float ang = (float)(2.0*PI) * threadIdx.x / 128.0f;
        c128[threadIdx.x] = cosf(ang);
        s128[threadIdx.x] = sinf(ang);
    }
    __syncthreads();
    for (int t = threadIdx.x; t < NFREQ*NB; t += blockDim.x) {
        int mf = t >> 7, b = t & 127;
        int mm = mf + 109; // == (mf-19) mod 128
        float re = 0.f, im = 0.f;
        for (int a = 0; a < NB; a++) {
            int k = (mm * a) & 127;
            float v = sx[b*129 + a];
            re += v * c128[k];
            im -= v * s128[k];
        }
        g_XF[((size_t)mf*(NBATCH*FI) + zi)*NB + b] = make_float2(re, im);
    }
}

// XL[lm][zi] = sum_b ws2T[lm][b] * XF[mf(lm)][zi][b]
__global__ void k_xl() {
    __shared__ float sw[NB];
    int lm = blockIdx.x;
    int zi0 = blockIdx.y * 32;
    if (threadIdx.x < NB) sw[threadIdx.x] = g_ws2T[lm*NB + threadIdx.x];
    __syncthreads();
    int l = l_from_lm(lm);
    int mf = lm - l*l - l + 19;
    int ziL = threadIdx.x >> 3, lane = threadIdx.x & 7;
    int zi = zi0 + ziL;
    float re = 0.f, im = 0.f;
    const float2* row = &g_XF[((size_t)mf*(NBATCH*FI) + zi)*NB];
    for (int b = lane; b < NB; b += 8) {
        float w = sw[b];
        float2 v = row[b];
        re += w * v.x;
        im += w * v.y;
    }
    #pragma unroll
    for (int off = 4; off; off >>= 1) {
        re += __shfl_down_sync(0xffffffffu, re, off, 8);
        im += __shfl_down_sync(0xffffffffu, im, off, 8);
    }
    if (lane == 0) g_XL[lm*(NBATCH*FI) + zi] = make_float2(re, im);
}

// ZL[z][s][o] = sum_i XL[l^2+mi][z][i] * CY[l^2+ni][i][o]
__global__ void k_zl() {
    int gid = blockIdx.x*blockDim.x + threadIdx.x;
    if (gid >= NBATCH*NS2*FO) return;
    int o = gid & 31;
    int rest = gid >> 5;
    int s = rest % NS2;
    int z = rest / NS2;
    int l = 0;
    while (s >= c_base[l+1]) l++;
    int r = s - c_base[l];
    int w = 2*l + 1;
    int mi = r / w, ni = r - mi*w;
    int lmm = l*l + mi, lmn = l*l + ni;
    const float2* xrow = &g_XL[lmm*(NBATCH*FI) + z*FI];
    const float2* crow = &g_CY[lmn*(FI*FO) + o];
    float re = 0.f, im = 0.f;
    #pragma unroll
    for (int i = 0; i < FI; i++) {
        float2 xv = xrow[i];
        float2 cy = crow[i*FO];
        re += xv.x*cy.x - xv.y*cy.y;
        im += xv.x*cy.y + xv.y*cy.x;
    }
    g_ZL[gid] = make_float2(re, im);
}

// Fused: OUT tile -> DFT over n -> DFT over m (real part) -> global out
__global__ void k_final(float* __restrict__ dout, const float* __restrict__ bias) {
    extern __shared__ float smf[];
    float2* sZL  = (float2*)smf;                 // NS2
    float2* sOUT = sZL + NS2;                    // 39*39 = 1521
    float2* sG1  = sOUT + NFREQ*NFREQ;           // 39*40 = 1560
    float*  ctab = (float*)(sG1 + NFREQ*TB);     // 40
    float*  stab = ctab + TB;                    // 40
    int z = blockIdx.x >> 5, o = blockIdx.x & 31;
    const int nt = blockDim.x;
    for (int t = threadIdx.x; t < NS2; t += nt)
        sZL[t] = g_ZL[((size_t)z*NS2 + t)*FO + o];
    if (threadIdx.x < TB) {
        float ang = (float)(2.0*PI) * threadIdx.x / (float)TB;
        ctab[threadIdx.x] = cosf(ang);
        stab[threadIdx.x] = sinf(ang);
    }
    float bv = bias[o];
    __syncthreads();

    for (int beta = 0; beta < TB; beta++) {
        // phase 1: spectral tile OUT[mf][nf] = sum_l dinv * ZL
        for (int t = threadIdx.x; t < NFREQ*NFREQ; t += nt) {
            int mf = t / NFREQ, nf = t - mf*NFREQ;
            int m = mf - 19, n = nf - 19;
            int am = abs(m), an = abs(n);
            int lmin = am > an ? am : an;
            float re = 0.f, im = 0.f;
            for (int l = lmin; l < LMAX; l++) {
                int w = 2*l + 1;
                int inner = (m + l)*w + (n + l);
                float d = g_dinv[40*c_base[l] + beta*w*w + inner];
                float2 v = sZL[c_base[l] + inner];
                re += d*v.x;
                im += d*v.y;
            }
            sOUT[t] = make_float2(re, im);
        }
        __syncthreads();
        // phase 2: DFT over n -> g
        for (int t = threadIdx.x; t < NFREQ*TB; t += nt) {
            int mf = t / TB, g = t - mf*TB;
            float re = 0.f, im = 0.f;
            const float2* row = &sOUT[mf*NFREQ];
            for (int nf = 0; nf < NFREQ; nf++) {
                int k = ((nf + 21) * g) % TB;
                float2 v = row[nf];
                float c = ctab[k], s = stab[k];
                re += v.x*c - v.y*s;
                im += v.x*s + v.y*c;
            }
            sG1[t] = make_float2(re, im);
        }
        __syncthreads();
        // phase 3: DFT over m -> a, real part, write
        size_t obase = (((size_t)(z*FO + o))*TB + beta)*TB*TB;
        for (int t = threadIdx.x; t < TB*TB; t += nt) {
            int a = t / TB, g = t - a*TB;
            float acc = bv;
            for (int mf = 0; mf < NFREQ; mf++) {
                int k = ((mf + 21) * a) % TB;
                float2 v = sG1[mf*TB + g];
                acc += v.x*ctab[k] - v.y*stab[k];
            }
            dout[obase + t] = acc;
        }
        __syncthreads();
    }
}

extern "C" void kernel_launch(void* const* d_in, const int* in_sizes, int n_in,
                              void* d_out, int out_size) {
    const float* x    = (const float*)d_in[0];
    const float* kern = (const float*)d_in[1];
    const float* bias = (const float*)d_in[2];
    float* out = (float*)d_out;

    const int smem_xf = NB*129*4 + 2*NB*4;                       // 67,072 B
    const int smem_fi = (NS2 + NFREQ*NFREQ + NFREQ*TB)*8 + 2*TB*4; // 110,248 B
    cudaFuncSetAttribute(k_xf, cudaFuncAttributeMaxDynamicSharedMemorySize, smem_xf);
    cudaFuncSetAttribute(k_final, cudaFuncAttributeMaxDynamicSharedMemorySize, smem_fi);

    k_tables<<<1, 128>>>();
    k_ws2<<<(NSPEC*NB + 255)/256, 256>>>();
    k_fk<<<(NSPEC*NGRID + 255)/256, 256>>>();
    k_dinv<<<(NDINV + 255)/256, 256>>>();
    k_y<<<(NSPEC*FI*FO + 255)/256, 256>>>(kern);
    k_xf<<<NBATCH*FI, 256, smem_xf>>>(x);
    k_xl<<<dim3(NSPEC, (NBATCH*FI)/32), 256>>>();
    k_zl<<<(NBATCH*NS2*FO + 255)/256, 256>>>();
    k_final<<<NBATCH*FO, 512, smem_fi>>>(out, bias);
}

// round 3
// speedup vs baseline: 1.8452x; 1.8452x over previous
#include <cuda_runtime.h>
#include <math.h>

#define PI 3.141592653589793238462643383279502884

#define NB    128     // 2*B_IN
#define NSPEC 400     // B_OUT^2
#define LMAX  20
#define NGRID 24
#define FI    16
#define FO    32
#define NBATCH 16
#define TB    40      // 2*B_INV
#define NFREQ 39
#define MHALF 20      // m = 0..19 (hermitian half)
#define NS2   10660
#define NDINV 426400

__constant__ int c_base[21] = {0,1,10,35,84,165,286,455,680,969,1330,1771,
                               2300,2925,3654,4495,5456,6545,7770,9139,10660};

// ---- device scratch ----
__device__ double g_lg[64];
__device__ double g_w[NB];
__device__ float  g_ws2T[NSPEC*NB];          // [lm][b]
__device__ float2 g_Fk[NSPEC*NGRID];
__device__ float  g_dinv[NDINV];
__device__ float2 g_CY[NSPEC*FI*FO];         // [lm][i][o]
__device__ float2 g_XF[MHALF*NBATCH*FI*NB];  // [m>=0][zi][b]
__device__ float2 g_XL[NSPEC*NBATCH*FI];     // [lm][zi]
__device__ float2 g_ZL[NBATCH*FO*NS2];       // [zo][s]  (coalesced for k_final)

__device__ __forceinline__ double wigner_d_fn(int l, int m, int n, double beta,
                                              const double* lg) {
    double cb = cos(0.5*beta), sb = sin(0.5*beta);
    double lcb = log(cb), lsb = log(sb);
    int s0 = max(0, n - m), s1 = min(l + n, l - m);
    double pref = 0.5*(lg[l+m] + lg[l-m] + lg[l+n] + lg[l-n]);
    double c0 = pref - (lg[l+n-s0] + lg[s0] + lg[m-n+s0] + lg[l-m-s0]);
    double t = exp(c0 + (double)(2*l + n - m - 2*s0)*lcb
                      + (double)(m - n + 2*s0)*lsb);
    if ((m - n + s0) & 1) t = -t;
    double r = (sb*sb)/(cb*cb);
    double val = 0.0;
    for (int s = s0;; ++s) {
        val += t;
        if (s >= s1) break;
        t *= -((double)((l+n-s)*(l-m-s)) * r) / (double)((s+1)*(m-n+s+1));
    }
    return val;
}

__device__ __forceinline__ int l_from_lm(int lm) {
    int l = 0;
    while ((l+1)*(l+1) <= lm) l++;
    return l;
}

// ---- constants kernels ----
__global__ void k_tables() {
    int t = threadIdx.x;
    if (t < 64) g_lg[t] = lgamma((double)t + 1.0);
    double theta = PI * (2.0*t + 1.0) / 256.0;
    double ssum = 0.0;
    for (int k = 0; k < 64; k++)
        ssum += sin((2.0*k + 1.0)*theta) / (2.0*k + 1.0);
    g_w[t] = (2.0/64.0) * sin(theta) * ssum;
}

__global__ void k_ws2() {
    __shared__ double lg[64];
    if (threadIdx.x < 64) lg[threadIdx.x] = g_lg[threadIdx.x];
    __syncthreads();
    int idx = blockIdx.x*blockDim.x + threadIdx.x;
    if (idx >= NSPEC*NB) return;
    int lm = idx >> 7, b = idx & 127;
    int l = l_from_lm(lm);
    int m = lm - l*l - l;
    double beta = PI * (2.0*b + 1.0) / 256.0;
    double d = wigner_d_fn(l, m, 0, beta, lg);
    g_ws2T[lm*NB + b] = (float)(d * g_w[b]);
}

__global__ void k_fk() {
    __shared__ double lg[64];
    if (threadIdx.x < 64) lg[threadIdx.x] = g_lg[threadIdx.x];
    __syncthreads();
    int idx = blockIdx.x*blockDim.x + threadIdx.x;
    if (idx >= NSPEC*NGRID) return;
    int lm = idx / NGRID, p = idx % NGRID;
    int l = l_from_lm(lm);
    int m = lm - l*l - l;
    int bi = p >> 3, ai = p & 7;
    double beta = (bi + 1) * PI / 24.0;
    double alpha = ai * (PI / 4.0);
    double d = wigner_d_fn(l, m, 0, beta, lg);
    double sa, ca;
    sincos((double)m * alpha, &sa, &ca);
    g_Fk[lm*NGRID + p] = make_float2((float)(d*ca), (float)(-d*sa));
}

__global__ void k_dinv() {
    __shared__ double lg[64];
    if (threadIdx.x < 64) lg[threadIdx.x] = g_lg[threadIdx.x];
    __syncthreads();
    int idx = blockIdx.x*blockDim.x + threadIdx.x;
    if (idx >= NDINV) return;
    int l = 0;
    while (idx >= 40*c_base[l+1]) l++;
    int rem = idx - 40*c_base[l];
    int w = 2*l + 1, w2 = w*w;
    int bidx = rem / w2;
    int r2 = rem - bidx*w2;
    int mi = r2 / w, ni = r2 - mi*w;
    double beta = PI * (2.0*bidx + 1.0) / 80.0;
    double d = (double)(2*l + 1) * wigner_d_fn(l, mi - l, ni - l, beta, lg);
    g_dinv[idx] = (float)d;
}

__global__ void k_y(const float* __restrict__ kern) {
    int idx = blockIdx.x*blockDim.x + threadIdx.x;
    if (idx >= NSPEC*FI*FO) return;
    int lm = idx >> 9;
    int io = idx & 511;
    const float SC = (float)(1.0/sqrt(15000.0));
    float re = 0.f, im = 0.f;
    #pragma unroll
    for (int p = 0; p < NGRID; p++) {
        float kv = kern[io*NGRID + p];
        float2 fk = g_Fk[lm*NGRID + p];
        re += kv * fk.x;
        im -= kv * fk.y;  // conj
    }
    g_CY[idx] = make_float2(SC*re, SC*im);
}

// XF[m][zi][b] for m in 0..19 only (hermitian: x real)
__global__ void __launch_bounds__(256) k_xf(const float* __restrict__ x) {
    extern __shared__ float sm[];
    float*  sx = sm;                          // 128*129
    float2* tw = (float2*)(sm + NB*129);      // 128
    int zi = blockIdx.x;
    const float* xr = x + (size_t)zi * NB * NB;
    for (int t = threadIdx.x; t < NB*NB; t += blockDim.x) {
        int b = t >> 7, a = t & 127;
        sx[b*129 + a] = xr[t];
    }
    if (threadIdx.x < NB) {
        float ang = (float)(2.0*PI) * threadIdx.x / 128.0f;
        tw[threadIdx.x] = make_float2(cosf(ang), sinf(ang));
    }
    __syncthreads();
    int b = threadIdx.x & 127;
    int half = threadIdx.x >> 7;  // 0/1 (blockDim=256)
    for (int it = 0; it < 10; it++) {
        int m = it*2 + half;
        float re = 0.f, im = 0.f;
        int k = 0;
        #pragma unroll 8
        for (int a = 0; a < NB; a++) {
            float v = sx[b*129 + a];
            float2 w = tw[k];
            re += v * w.x;
            im -= v * w.y;   // e^{-i m a 2pi/128}
            k = (k + m) & 127;
        }
        g_XF[((size_t)m*(NBATCH*FI) + zi)*NB + b] = make_float2(re, im);
    }
}

// XL[lm][zi] = sum_b ws2T[lm][b] * XF[|m|][zi][b] (conj if m<0)
__global__ void k_xl() {
    __shared__ float sw[NB];
    int lm = blockIdx.x;
    int zi0 = blockIdx.y * 32;
    if (threadIdx.x < NB) sw[threadIdx.x] = g_ws2T[lm*NB + threadIdx.x];
    __syncthreads();
    int l = l_from_lm(lm);
    int m = lm - l*l - l;
    int rm = m < 0 ? -m : m;
    float sgn = m < 0 ? -1.f : 1.f;
    int ziL = threadIdx.x >> 3, lane = threadIdx.x & 7;
    int zi = zi0 + ziL;
    float re = 0.f, im = 0.f;
    const float2* row = &g_XF[((size_t)rm*(NBATCH*FI) + zi)*NB];
    for (int b = lane; b < NB; b += 8) {
        float w = sw[b];
        float2 v = row[b];
        re += w * v.x;
        im += w * v.y * sgn;
    }
    #pragma unroll
    for (int off = 4; off; off >>= 1) {
        re += __shfl_down_sync(0xffffffffu, re, off, 8);
        im += __shfl_down_sync(0xffffffffu, im, off, 8);
    }
    if (lane == 0) g_XL[lm*(NBATCH*FI) + zi] = make_float2(re, im);
}

// ZL[zo][s]: block per (l, z), CY l-slice cached in shared
__global__ void __launch_bounds__(256) k_zl() {
    extern __shared__ float smz[];
    int l = blockIdx.x, z = blockIdx.y;
    int w = 2*l + 1, w2 = w*w;
    float2* CYs = (float2*)smz;          // w rows, stride 513 float2
    float2* XLs = CYs + w*513;           // w rows, stride 17
    for (int t = threadIdx.x; t < w*512; t += blockDim.x) {
        int ni = t >> 9, c = t & 511;
        CYs[ni*513 + c] = g_CY[((l*l + ni) << 9) + c];
    }
    for (int t = threadIdx.x; t < w*FI; t += blockDim.x) {
        int mi = t >> 4, i = t & 15;
        XLs[mi*17 + i] = g_XL[(size_t)(l*l + mi)*(NBATCH*FI) + z*FI + i];
    }
    __syncthreads();
    int tot = w2 * FO;
    for (int idx = threadIdx.x; idx < tot; idx += blockDim.x) {
        int o = idx / w2;
        int r = idx - o*w2;
        int mi = r / w, ni = r - mi*w;
        float re = 0.f, im = 0.f;
        #pragma unroll
        for (int i = 0; i < FI; i++) {
            float2 xv = XLs[mi*17 + i];
            float2 cy = CYs[ni*513 + i*32 + o];
            re += xv.x*cy.x - xv.y*cy.y;
            im += xv.x*cy.y + xv.y*cy.x;
        }
        g_ZL[((size_t)(z*FO + o))*NS2 + c_base[l] + r] = make_float2(re, im);
    }
}

// Fused synthesis, hermitian-half spectral tile.
// grid: (z*FO+o)*2 + betahalf ; block 512
__global__ void __launch_bounds__(512) k_final(float* __restrict__ dout,
                                               const float* __restrict__ bias) {
    extern __shared__ float smf[];
    float2* sZL  = (float2*)smf;                  // NS2
    float2* sOUT = sZL + NS2;                     // 20*39
    float2* sG1  = sOUT + MHALF*NFREQ;            // 20*40
    float2* sW2  = sG1 + MHALF*TB;                // [nf][g] 39*40
    float*  sCt  = (float*)(sW2 + NFREQ*TB);      // [a][m-1] 40*19
    float*  sSt  = sCt + TB*19;                   // 40*19
    int zo = blockIdx.x >> 1;
    int half = blockIdx.x & 1;
    int o = zo & 31;
    const int nt = blockDim.x;

    const float2* zl = g_ZL + (size_t)zo * NS2;
    for (int t = threadIdx.x; t < NS2; t += nt) sZL[t] = zl[t];
    const float W0 = (float)(2.0*PI/40.0);
    for (int t = threadIdx.x; t < NFREQ*TB; t += nt) {
        int nf = t / TB, g = t - nf*TB;
        int k = ((nf + 21) * g) % TB;
        float ang = W0 * k;
        sW2[t] = make_float2(cosf(ang), sinf(ang));
    }
    for (int t = threadIdx.x; t < TB*19; t += nt) {
        int a = t / 19, mm = t - a*19 + 1;
        int k = (mm * a) % TB;
        float ang = W0 * k;
        sCt[t] = 2.0f*cosf(ang);
        sSt[t] = 2.0f*sinf(ang);
    }
    float bv = bias[o];
    __syncthreads();

    int g400 = threadIdx.x % TB;        // for phases 2/3
    int q400 = threadIdx.x / TB;        // 0..12 (only <10 used)
    bool act = (threadIdx.x < 400);

    for (int bb = 0; bb < 20; bb++) {
        int beta = half*20 + bb;
        // phase 1: OUT[m][nf] for m in 0..19
        for (int t = threadIdx.x; t < MHALF*NFREQ; t += nt) {
            int m = t / NFREQ, nf = t - m*NFREQ;
            int n = nf - 19;
            int an = n < 0 ? -n : n;
            int lmin = m > an ? m : an;
            float re = 0.f, im = 0.f;
            for (int l = lmin; l < LMAX; l++) {
                int w = 2*l + 1;
                int inner = (m + l)*w + (n + l);
                float d = g_dinv[40*c_base[l] + beta*w*w + inner];
                float2 v = sZL[c_base[l] + inner];
                re += d*v.x;
                im += d*v.y;
            }
            sOUT[t] = make_float2(re, im);
        }
        __syncthreads();
        // phase 2: G1[m][g] = sum_nf OUT[m][nf] * W2[nf][g], m tiles {q, q+10}
        if (act) {
            int m0 = q400, m1 = q400 + 10;
            float r0=0.f, i0=0.f, r1=0.f, i1=0.f;
            #pragma unroll 3
            for (int nf = 0; nf < NFREQ; nf++) {
                float2 w = sW2[nf*TB + g400];
                float2 a0 = sOUT[m0*NFREQ + nf];
                float2 a1 = sOUT[m1*NFREQ + nf];
                r0 += a0.x*w.x - a0.y*w.y;
                i0 += a0.x*w.y + a0.y*w.x;
                r1 += a1.x*w.x - a1.y*w.y;
                i1 += a1.x*w.y + a1.y*w.x;
            }
            sG1[m0*TB + g400] = make_float2(r0, i0);
            sG1[m1*TB + g400] = make_float2(r1, i1);
        }
        __syncthreads();
        // phase 3: f[a][g] = bias + Re(G1[0][g]) + sum_{m>=1} (G1r*Ct - G1i*St)
        if (act) {
            float base = bv + sG1[g400].x;
            float acc0 = base, acc1 = base, acc2 = base, acc3 = base;
            #pragma unroll 4
            for (int m = 1; m < MHALF; m++) {
                float2 v = sG1[m*TB + g400];
                int ti = (m - 1);
                float c0 = sCt[(q400      )*19 + ti], s0 = sSt[(q400      )*19 + ti];
                float c1 = sCt[(q400 + 10)*19 + ti], s1 = sSt[(q400 + 10)*19 + ti];
                float c2 = sCt[(q400 + 20)*19 + ti], s2 = sSt[(q400 + 20)*19 + ti];
                float c3 = sCt[(q400 + 30)*19 + ti], s3 = sSt[(q400 + 30)*19 + ti];
                acc0 += v.x*c0 - v.y*s0;
                acc1 += v.x*c1 - v.y*s1;
                acc2 += v.x*c2 - v.y*s2;
                acc3 += v.x*c3 - v.y*s3;
            }
            size_t ob = ((size_t)zo*TB + beta)*TB*TB;
            dout[ob + (q400      )*TB + g400] = acc0;
            dout[ob + (q400 + 10)*TB + g400] = acc1;
            dout[ob + (q400 + 20)*TB + g400] = acc2;
            dout[ob + (q400 + 30)*TB + g400] = acc3;
        }
        __syncthreads();
    }
}

extern "C" void kernel_launch(void* const* d_in, const int* in_sizes, int n_in,
                              void* d_out, int out_size) {
    const float* x    = (const float*)d_in[0];
    const float* kern = (const float*)d_in[1];
    const float* bias = (const float*)d_in[2];
    float* out = (float*)d_out;

    const int smem_xf = NB*129*4 + NB*8;                       // 67,072
    const int smem_zl = 39*513*8 + 39*17*8;                    // 165,360
    const int smem_fi = (NS2 + MHALF*NFREQ + MHALF*TB + NFREQ*TB)*8
                        + 2*TB*19*4;                           // 116,480
    cudaFuncSetAttribute(k_xf,    cudaFuncAttributeMaxDynamicSharedMemorySize, smem_xf);
    cudaFuncSetAttribute(k_zl,    cudaFuncAttributeMaxDynamicSharedMemorySize, smem_zl);
    cudaFuncSetAttribute(k_final, cudaFuncAttributeMaxDynamicSharedMemorySize, smem_fi);

    k_tables<<<1, 128>>>();
    k_ws2<<<(NSPEC*NB + 255)/256, 256>>>();
    k_fk<<<(NSPEC*NGRID + 255)/256, 256>>>();
    k_dinv<<<(NDINV + 255)/256, 256>>>();
    k_y<<<(NSPEC*FI*FO + 255)/256, 256>>>(kern);
    k_xf<<<NBATCH*FI, 256, smem_xf>>>(x);
    k_xl<<<dim3(NSPEC, (NBATCH*FI)/32), 256>>>();
    k_zl<<<dim3(LMAX, NBATCH), 256, smem_zl>>>();
    k_final<<<NBATCH*FO*2, 512, smem_fi>>>(out, bias);
}

// round 4
// speedup vs baseline: 3.1483x; 1.7062x over previous
#include <cuda_runtime.h>
#include <math.h>

#define PI 3.141592653589793238462643383279502884

#define NB    128     // 2*B_IN
#define NSPEC 400     // B_OUT^2
#define LMAX  20
#define NGRID 24
#define FI    16
#define FO    32
#define NBATCH 16
#define TB    40      // 2*B_INV
#define NFREQ 39
#define MHALF 20      // m = 0..19 (hermitian half)
#define NS2P  5530    // sum_{l<20} (l+1)(2l+1)  (m>=0 packed)
#define NDINV2 221200 // 40 * NS2P

// packed offsets cb2[l] = sum_{j<l} (j+1)(2j+1)
__constant__ int cb2[21] = {0,1,7,22,50,95,161,252,372,525,715,946,1222,
                            1547,1925,2360,2856,3417,4047,4750,5530};

// ---- device scratch ----
__device__ double g_lg[64];
__device__ double g_w[NB];
__device__ float  g_ws2T[NSPEC*NB];          // [lm][b]
__device__ float2 g_Fk[NSPEC*NGRID];
__device__ float  g_dinv[NDINV2];            // packed [l][beta][m=0..l][ni]
__device__ float2 g_CY[NSPEC*FI*FO];         // [lm][i][o]
__device__ float2 g_XF[MHALF*NBATCH*FI*NB];  // [m>=0][zi][b]
__device__ float2 g_XL[NSPEC*NBATCH*FI];     // [lm][zi]
__device__ float2 g_ZL[NBATCH*FO*NS2P];      // [zo][packed s]

__device__ __forceinline__ double wigner_d_fn(int l, int m, int n, double beta,
                                              const double* lg) {
    double cb = cos(0.5*beta), sb = sin(0.5*beta);
    double lcb = log(cb), lsb = log(sb);
    int s0 = max(0, n - m), s1 = min(l + n, l - m);
    double pref = 0.5*(lg[l+m] + lg[l-m] + lg[l+n] + lg[l-n]);
    double c0 = pref - (lg[l+n-s0] + lg[s0] + lg[m-n+s0] + lg[l-m-s0]);
    double t = exp(c0 + (double)(2*l + n - m - 2*s0)*lcb
                      + (double)(m - n + 2*s0)*lsb);
    if ((m - n + s0) & 1) t = -t;
    double r = (sb*sb)/(cb*cb);
    double val = 0.0;
    for (int s = s0;; ++s) {
        val += t;
        if (s >= s1) break;
        t *= -((double)((l+n-s)*(l-m-s)) * r) / (double)((s+1)*(m-n+s+1));
    }
    return val;
}

__device__ __forceinline__ int l_from_lm(int lm) {
    int l = 0;
    while ((l+1)*(l+1) <= lm) l++;
    return l;
}

// ---- constants kernels ----
__global__ void k_tables() {
    int t = threadIdx.x;
    if (t < 64) g_lg[t] = lgamma((double)t + 1.0);
    double theta = PI * (2.0*t + 1.0) / 256.0;
    double ssum = 0.0;
    for (int k = 0; k < 64; k++)
        ssum += sin((2.0*k + 1.0)*theta) / (2.0*k + 1.0);
    g_w[t] = (2.0/64.0) * sin(theta) * ssum;
}

__global__ void k_ws2() {
    __shared__ double lg[64];
    if (threadIdx.x < 64) lg[threadIdx.x] = g_lg[threadIdx.x];
    __syncthreads();
    int idx = blockIdx.x*blockDim.x + threadIdx.x;
    if (idx >= NSPEC*NB) return;
    int lm = idx >> 7, b = idx & 127;
    int l = l_from_lm(lm);
    int m = lm - l*l - l;
    double beta = PI * (2.0*b + 1.0) / 256.0;
    double d = wigner_d_fn(l, m, 0, beta, lg);
    g_ws2T[lm*NB + b] = (float)(d * g_w[b]);
}

__global__ void k_fk() {
    __shared__ double lg[64];
    if (threadIdx.x < 64) lg[threadIdx.x] = g_lg[threadIdx.x];
    __syncthreads();
    int idx = blockIdx.x*blockDim.x + threadIdx.x;
    if (idx >= NSPEC*NGRID) return;
    int lm = idx / NGRID, p = idx % NGRID;
    int l = l_from_lm(lm);
    int m = lm - l*l - l;
    int bi = p >> 3, ai = p & 7;
    double beta = (bi + 1) * PI / 24.0;
    double alpha = ai * (PI / 4.0);
    double d = wigner_d_fn(l, m, 0, beta, lg);
    double sa, ca;
    sincos((double)m * alpha, &sa, &ca);
    g_Fk[lm*NGRID + p] = make_float2((float)(d*ca), (float)(-d*sa));
}

// packed dinv: [l][beta][m=0..l][ni=0..2l]; value (2l+1)*d^l_{m, ni-l}(beta)
__global__ void k_dinv() {
    __shared__ double lg[64];
    if (threadIdx.x < 64) lg[threadIdx.x] = g_lg[threadIdx.x];
    __syncthreads();
    int idx = blockIdx.x*blockDim.x + threadIdx.x;
    if (idx >= NDINV2) return;
    int l = 0;
    while (idx >= 40*cb2[l+1]) l++;
    int rem = idx - 40*cb2[l];
    int w = 2*l + 1;
    int blk = (l+1)*w;
    int bidx = rem / blk;
    int r2 = rem - bidx*blk;
    int mr = r2 / w, ni = r2 - mr*w;
    double beta = PI * (2.0*bidx + 1.0) / 80.0;
    double d = (double)(2*l + 1) * wigner_d_fn(l, mr, ni - l, beta, lg);
    g_dinv[idx] = (float)d;
}

__global__ void k_y(const float* __restrict__ kern) {
    int idx = blockIdx.x*blockDim.x + threadIdx.x;
    if (idx >= NSPEC*FI*FO) return;
    int lm = idx >> 9;
    int io = idx & 511;
    const float SC = (float)(1.0/sqrt(15000.0));
    float re = 0.f, im = 0.f;
    #pragma unroll
    for (int p = 0; p < NGRID; p++) {
        float kv = kern[io*NGRID + p];
        float2 fk = g_Fk[lm*NGRID + p];
        re += kv * fk.x;
        im -= kv * fk.y;  // conj
    }
    g_CY[idx] = make_float2(SC*re, SC*im);
}

// XF[m][zi][b] for m in 0..19 only (hermitian: x real)
__global__ void __launch_bounds__(256) k_xf(const float* __restrict__ x) {
    extern __shared__ float sm[];
    float*  sx = sm;                          // 128*129
    float2* tw = (float2*)(sm + NB*129);      // 128
    int zi = blockIdx.x;
    const float* xr = x + (size_t)zi * NB * NB;
    for (int t = threadIdx.x; t < NB*NB; t += blockDim.x) {
        int b = t >> 7, a = t & 127;
        sx[b*129 + a] = xr[t];
    }
    if (threadIdx.x < NB) {
        float ang = (float)(2.0*PI) * threadIdx.x / 128.0f;
        tw[threadIdx.x] = make_float2(cosf(ang), sinf(ang));
    }
    __syncthreads();
    int b = threadIdx.x & 127;
    int half = threadIdx.x >> 7;
    for (int it = 0; it < 10; it++) {
        int m = it*2 + half;
        float re = 0.f, im = 0.f;
        int k = 0;
        #pragma unroll 8
        for (int a = 0; a < NB; a++) {
            float v = sx[b*129 + a];
            float2 w = tw[k];
            re += v * w.x;
            im -= v * w.y;
            k = (k + m) & 127;
        }
        g_XF[((size_t)m*(NBATCH*FI) + zi)*NB + b] = make_float2(re, im);
    }
}

// XL[lm][zi] = sum_b ws2T[lm][b] * XF[|m|][zi][b] (conj if m<0)
__global__ void k_xl() {
    __shared__ float sw[NB];
    int lm = blockIdx.x;
    int zi0 = blockIdx.y * 32;
    if (threadIdx.x < NB) sw[threadIdx.x] = g_ws2T[lm*NB + threadIdx.x];
    __syncthreads();
    int l = l_from_lm(lm);
    int m = lm - l*l - l;
    int rm = m < 0 ? -m : m;
    float sgn = m < 0 ? -1.f : 1.f;
    int ziL = threadIdx.x >> 3, lane = threadIdx.x & 7;
    int zi = zi0 + ziL;
    float re = 0.f, im = 0.f;
    const float2* row = &g_XF[((size_t)rm*(NBATCH*FI) + zi)*NB];
    for (int b = lane; b < NB; b += 8) {
        float w = sw[b];
        float2 v = row[b];
        re += w * v.x;
        im += w * v.y * sgn;
    }
    #pragma unroll
    for (int off = 4; off; off >>= 1) {
        re += __shfl_down_sync(0xffffffffu, re, off, 8);
        im += __shfl_down_sync(0xffffffffu, im, off, 8);
    }
    if (lane == 0) g_XL[lm*(NBATCH*FI) + zi] = make_float2(re, im);
}

// ZL packed (m>=0 rows only): block per (l, z)
__global__ void __launch_bounds__(256) k_zl() {
    extern __shared__ float smz[];
    int l = blockIdx.x, z = blockIdx.y;
    int w = 2*l + 1;
    int rows = l + 1;
    float2* CYs = (float2*)smz;          // w rows, stride 513
    float2* XLs = CYs + 39*513;          // rows rows, stride 17
    for (int t = threadIdx.x; t < w*512; t += blockDim.x) {
        int ni = t >> 9, c = t & 511;
        CYs[ni*513 + c] = g_CY[((l*l + ni) << 9) + c];
    }
    for (int t = threadIdx.x; t < rows*FI; t += blockDim.x) {
        int mr = t >> 4, i = t & 15;
        XLs[mr*17 + i] = g_XL[(size_t)(l*l + l + mr)*(NBATCH*FI) + z*FI + i];
    }
    __syncthreads();
    int blk = rows * w;
    int tot = blk * FO;
    for (int idx = threadIdx.x; idx < tot; idx += blockDim.x) {
        int o = idx / blk;
        int r = idx - o*blk;
        int mr = r / w, ni = r - mr*w;
        float re = 0.f, im = 0.f;
        #pragma unroll
        for (int i = 0; i < FI; i++) {
            float2 xv = XLs[mr*17 + i];
            float2 cy = CYs[ni*513 + i*32 + o];
            re += xv.x*cy.x - xv.y*cy.y;
            im += xv.x*cy.y + xv.y*cy.x;
        }
        g_ZL[((size_t)(z*FO + o))*NS2P + cb2[l] + r] = make_float2(re, im);
    }
}

// Fused synthesis, hermitian-half spectral tile, beta-pair tiled.
// grid: (z*FO+o)*2 + betahalf ; block 512, 2 blocks/SM
__global__ void __launch_bounds__(512, 2) k_final(float* __restrict__ dout,
                                                  const float* __restrict__ bias) {
    extern __shared__ float smf[];
    float2* sZL  = (float2*)smf;                  // NS2P = 5530
    float2* sOUT = sZL + NS2P;                    // 2 * 20*39
    float2* sG1  = sOUT + 2*MHALF*NFREQ;          // 2 * 20*40
    float2* sW2  = sG1 + 2*MHALF*TB;              // [nf][g] 39*40
    float*  sCt  = (float*)(sW2 + NFREQ*TB);      // [a][m-1] 40*19
    float*  sSt  = sCt + TB*19;                   // 40*19
    int zo = blockIdx.x >> 1;
    int half = blockIdx.x & 1;
    int o = zo & 31;
    const int nt = blockDim.x;

    const float2* zl = g_ZL + (size_t)zo * NS2P;
    for (int t = threadIdx.x; t < NS2P; t += nt) sZL[t] = zl[t];
    const float W0 = (float)(2.0*PI/40.0);
    for (int t = threadIdx.x; t < NFREQ*TB; t += nt) {
        int nf = t / TB, g = t - nf*TB;
        int k = ((nf + 21) * g) % TB;
        float ang = W0 * k;
        sW2[t] = make_float2(cosf(ang), sinf(ang));
    }
    for (int t = threadIdx.x; t < TB*19; t += nt) {
        int a = t / 19, mm = t - a*19 + 1;
        int k = (mm * a) % TB;
        float ang = W0 * k;
        sCt[t] = 2.0f*cosf(ang);
        sSt[t] = 2.0f*sinf(ang);
    }
    float bv = bias[o];
    __syncthreads();

    int g400 = threadIdx.x % TB;
    int q400 = threadIdx.x / TB;        // 0..12 (<10 active)
    bool act = (threadIdx.x < 400);

    for (int p = 0; p < 10; p++) {
        int beta0 = half*20 + 2*p;      // pair (beta0, beta0+1)
        // phase 1: OUT[b2][m][nf], m = 0..19, both betas
        for (int t = threadIdx.x; t < 2*MHALF*NFREQ; t += nt) {
            int b2 = (t >= MHALF*NFREQ);
            int tt = t - b2*MHALF*NFREQ;
            int m = tt / NFREQ, nf = tt - m*NFREQ;
            int n = nf - 19;
            int an = n < 0 ? -n : n;
            int lmin = m > an ? m : an;
            int beta = beta0 + b2;
            float re = 0.f, im = 0.f;
            for (int l = lmin; l < LMAX; l++) {
                int w = 2*l + 1;
                int off = m*w + (n + l);
                float d = g_dinv[40*cb2[l] + beta*(l+1)*w + off];
                float2 v = sZL[cb2[l] + off];
                re += d*v.x;
                im += d*v.y;
            }
            sOUT[t] = make_float2(re, im);
        }
        __syncthreads();
        // phase 2: G1[b2][m][g] = sum_nf OUT[b2][m][nf]*W2[nf][g]; m in {q,q+10}, 2 betas
        if (act) {
            int m0 = q400, m1 = q400 + 10;
            float r00=0.f,i00=0.f, r01=0.f,i01=0.f;
            float r10=0.f,i10=0.f, r11=0.f,i11=0.f;
            #pragma unroll 3
            for (int nf = 0; nf < NFREQ; nf++) {
                float2 w = sW2[nf*TB + g400];
                float2 a00 = sOUT[m0*NFREQ + nf];
                float2 a10 = sOUT[m1*NFREQ + nf];
                float2 a01 = sOUT[MHALF*NFREQ + m0*NFREQ + nf];
                float2 a11 = sOUT[MHALF*NFREQ + m1*NFREQ + nf];
                r00 += a00.x*w.x - a00.y*w.y; i00 += a00.x*w.y + a00.y*w.x;
                r10 += a10.x*w.x - a10.y*w.y; i10 += a10.x*w.y + a10.y*w.x;
                r01 += a01.x*w.x - a01.y*w.y; i01 += a01.x*w.y + a01.y*w.x;
                r11 += a11.x*w.x - a11.y*w.y; i11 += a11.x*w.y + a11.y*w.x;
            }
            sG1[m0*TB + g400] = make_float2(r00, i00);
            sG1[m1*TB + g400] = make_float2(r10, i10);
            sG1[MHALF*TB + m0*TB + g400] = make_float2(r01, i01);
            sG1[MHALF*TB + m1*TB + g400] = make_float2(r11, i11);
        }
        __syncthreads();
        // phase 3: f[a][g] = bias + Re(G1[0][g]) + sum_{m>=1}(G1r*Ct - G1i*St); 2 betas
        if (act) {
            float base0 = bv + sG1[g400].x;
            float base1 = bv + sG1[MHALF*TB + g400].x;
            float a0_0 = base0, a1_0 = base0, a2_0 = base0, a3_0 = base0;
            float a0_1 = base1, a1_1 = base1, a2_1 = base1, a3_1 = base1;
            #pragma unroll 4
            for (int m = 1; m < MHALF; m++) {
                float2 v0 = sG1[m*TB + g400];
                float2 v1 = sG1[MHALF*TB + m*TB + g400];
                int ti = m - 1;
                float c0 = sCt[(q400      )*19 + ti], s0 = sSt[(q400      )*19 + ti];
                float c1 = sCt[(q400 + 10)*19 + ti], s1 = sSt[(q400 + 10)*19 + ti];
                float c2 = sCt[(q400 + 20)*19 + ti], s2 = sSt[(q400 + 20)*19 + ti];
                float c3 = sCt[(q400 + 30)*19 + ti], s3 = sSt[(q400 + 30)*19 + ti];
                a0_0 += v0.x*c0 - v0.y*s0;  a0_1 += v1.x*c0 - v1.y*s0;
                a1_0 += v0.x*c1 - v0.y*s1;  a1_1 += v1.x*c1 - v1.y*s1;
                a2_0 += v0.x*c2 - v0.y*s2;  a2_1 += v1.x*c2 - v1.y*s2;
                a3_0 += v0.x*c3 - v0.y*s3;  a3_1 += v1.x*c3 - v1.y*s3;
            }
            size_t ob0 = ((size_t)zo*TB + beta0)*TB*TB;
            size_t ob1 = ob0 + TB*TB;
            dout[ob0 + (q400      )*TB + g400] = a0_0;
            dout[ob0 + (q400 + 10)*TB + g400] = a1_0;
            dout[ob0 + (q400 + 20)*TB + g400] = a2_0;
            dout[ob0 + (q400 + 30)*TB + g400] = a3_0;
            dout[ob1 + (q400      )*TB + g400] = a0_1;
            dout[ob1 + (q400 + 10)*TB + g400] = a1_1;
            dout[ob1 + (q400 + 20)*TB + g400] = a2_1;
            dout[ob1 + (q400 + 30)*TB + g400] = a3_1;
        }
        __syncthreads();
    }
}

extern "C" void kernel_launch(void* const* d_in, const int* in_sizes, int n_in,
                              void* d_out, int out_size) {
    const float* x    = (const float*)d_in[0];
    const float* kern = (const float*)d_in[1];
    const float* bias = (const float*)d_in[2];
    float* out = (float*)d_out;

    const int smem_xf = NB*129*4 + NB*8;                         // 67,072
    const int smem_zl = 39*513*8 + 20*17*8;                      // 162,776
    const int smem_fi = (NS2P + 2*MHALF*NFREQ + 2*MHALF*TB + NFREQ*TB)*8
                        + 2*TB*19*4;                             // 88,080
    cudaFuncSetAttribute(k_xf,    cudaFuncAttributeMaxDynamicSharedMemorySize, smem_xf);
    cudaFuncSetAttribute(k_zl,    cudaFuncAttributeMaxDynamicSharedMemorySize, smem_zl);
    cudaFuncSetAttribute(k_final, cudaFuncAttributeMaxDynamicSharedMemorySize, smem_fi);

    k_tables<<<1, 128>>>();
    k_ws2<<<(NSPEC*NB + 255)/256, 256>>>();
    k_fk<<<(NSPEC*NGRID + 255)/256, 256>>>();
    k_dinv<<<(NDINV2 + 255)/256, 256>>>();
    k_y<<<(NSPEC*FI*FO + 255)/256, 256>>>(kern);
    k_xf<<<NBATCH*FI, 256, smem_xf>>>(x);
    k_xl<<<dim3(NSPEC, (NBATCH*FI)/32), 256>>>();
    k_zl<<<dim3(LMAX, NBATCH), 256, smem_zl>>>();
    k_final<<<NBATCH*FO*2, 512, smem_fi>>>(out, bias);
}